// round 1
// baseline (speedup 1.0000x reference)
#include <cuda_runtime.h>
#include <cstdint>
#include <cstddef>

#define B_ 256
#define T_ 512
#define I_ 512
#define H_ 1024
#define O_ 128

typedef unsigned long long ull;

union F2U { float2 f; ull u; };

__device__ __forceinline__ ull pack2(float lo, float hi) {
    ull r; asm("mov.b64 %0, {%1, %2};" : "=l"(r) : "f"(lo), "f"(hi)); return r;
}
__device__ __forceinline__ void fma2(ull &acc, ull a, ull b) {
    asm("fma.rn.f32x2 %0, %1, %2, %0;" : "+l"(acc) : "l"(a), "l"(b));
}

// ---------------------------------------------------------------------------
// Generic C = A @ B^T + bias  (A: MxK row-major lda, B: NxK row-major ldb)
// 128x128 CTA tile, BK=8, 256 threads, 8x8 per thread via packed f32x2.
// All dims must divide evenly (they do for this problem).
// ---------------------------------------------------------------------------
__global__ __launch_bounds__(256, 2)
void gemm_nt_128(const float* __restrict__ A, int lda,
                 const float* __restrict__ Bm, int ldb,
                 const float* __restrict__ bias,
                 float* __restrict__ C, int ldc, int K)
{
    __shared__ float As[8][128];
    __shared__ float Bs[8][128];
    const int bm = blockIdx.x * 128;
    const int bn = blockIdx.y * 128;
    const int tid = threadIdx.x;
    const int tx = tid & 15;   // n direction (16 threads x 8 cols)
    const int ty = tid >> 4;   // m direction (16 threads x 8 rows)
    const int lrow = tid >> 1;        // 0..127
    const int lcol = (tid & 1) * 4;   // 0 or 4

    const float* Ap = A + (size_t)(bm + lrow) * lda + lcol;
    const float* Bp = Bm + (size_t)(bn + lrow) * ldb + lcol;

    ull acc[8][4];
#pragma unroll
    for (int i = 0; i < 8; i++)
#pragma unroll
        for (int j = 0; j < 4; j++) acc[i][j] = 0ULL;

    for (int k0 = 0; k0 < K; k0 += 8) {
        float4 av = *reinterpret_cast<const float4*>(Ap + k0);
        float4 bv = *reinterpret_cast<const float4*>(Bp + k0);
        As[lcol + 0][lrow] = av.x; As[lcol + 1][lrow] = av.y;
        As[lcol + 2][lrow] = av.z; As[lcol + 3][lrow] = av.w;
        Bs[lcol + 0][lrow] = bv.x; Bs[lcol + 1][lrow] = bv.y;
        Bs[lcol + 2][lrow] = bv.z; Bs[lcol + 3][lrow] = bv.w;
        __syncthreads();
#pragma unroll
        for (int kk = 0; kk < 8; kk++) {
            float4 a0 = *reinterpret_cast<const float4*>(&As[kk][ty * 8]);
            float4 a1 = *reinterpret_cast<const float4*>(&As[kk][ty * 8 + 4]);
            const ull* bp = reinterpret_cast<const ull*>(&Bs[kk][tx * 8]);
            ull b0 = bp[0], b1 = bp[1], b2 = bp[2], b3 = bp[3];
            float am[8] = {a0.x, a0.y, a0.z, a0.w, a1.x, a1.y, a1.z, a1.w};
#pragma unroll
            for (int i = 0; i < 8; i++) {
                ull ad = pack2(am[i], am[i]);
                fma2(acc[i][0], ad, b0);
                fma2(acc[i][1], ad, b1);
                fma2(acc[i][2], ad, b2);
                fma2(acc[i][3], ad, b3);
            }
        }
        __syncthreads();
    }

    float2 bias2[4];
#pragma unroll
    for (int j = 0; j < 4; j++)
        bias2[j] = *reinterpret_cast<const float2*>(&bias[bn + tx * 8 + j * 2]);

#pragma unroll
    for (int i = 0; i < 8; i++) {
        float* Crow = C + (size_t)(bm + ty * 8 + i) * ldc + bn + tx * 8;
#pragma unroll
        for (int j = 0; j < 4; j++) {
            F2U u; u.u = acc[i][j];
            u.f.x += bias2[j].x;
            u.f.y += bias2[j].y;
            *reinterpret_cast<float2*>(Crow + j * 2) = u.f;
        }
    }
}

// ---------------------------------------------------------------------------
// One recurrence step:
//   hid[:, t, :] = relu( hid[:, t, :] (=xw_t) + hid[:, t-1, :] @ W_h^T + b_h )
// hid layout (B, T, H); row (b, tt) at hid + b*T*H + tt*H.
// CTA tile: 32 (batch) x 64 (n), BK=16, 256 threads, 2x4 outputs/thread
// (2 n-pairs via f32x2). Grid (8, 16) = 128 CTAs (one wave).
// ---------------------------------------------------------------------------
__global__ __launch_bounds__(256, 1)
void rnn_step(const float* __restrict__ Wh, const float* __restrict__ bh,
              float* __restrict__ hid, int t)
{
    __shared__ float As[16][32];
    __shared__ float Bs[16][64];
    const int bm = blockIdx.x * 32;
    const int bn = blockIdx.y * 64;
    const int tid = threadIdx.x;
    const int tx = tid & 15;   // n: 16 threads x 4 cols
    const int ty = tid >> 4;   // m: 16 threads x 2 rows
    const size_t SR = (size_t)T_ * H_;

    ull acc[2][2] = {0ULL, 0ULL, 0ULL, 0ULL};

    if (t > 0) {
        const int brow = tid >> 2;         // 0..63 (B tile); 0..31 for A (tid<128)
        const int kcol = (tid & 3) * 4;    // 0,4,8,12
        const float* Bp = Wh + (size_t)(bn + brow) * H_ + kcol;
        const float* Ap = nullptr;
        if (tid < 128)
            Ap = hid + (size_t)(bm + brow) * SR + (size_t)(t - 1) * H_ + kcol;

        for (int k0 = 0; k0 < H_; k0 += 16) {
            if (tid < 128) {
                float4 av = *reinterpret_cast<const float4*>(Ap + k0);
                As[kcol + 0][brow] = av.x; As[kcol + 1][brow] = av.y;
                As[kcol + 2][brow] = av.z; As[kcol + 3][brow] = av.w;
            }
            float4 bv = *reinterpret_cast<const float4*>(Bp + k0);
            Bs[kcol + 0][brow] = bv.x; Bs[kcol + 1][brow] = bv.y;
            Bs[kcol + 2][brow] = bv.z; Bs[kcol + 3][brow] = bv.w;
            __syncthreads();
#pragma unroll
            for (int kk = 0; kk < 16; kk++) {
                float2 a2 = *reinterpret_cast<const float2*>(&As[kk][ty * 2]);
                const ull* bp2 = reinterpret_cast<const ull*>(&Bs[kk][tx * 4]);
                ull b0 = bp2[0], b1 = bp2[1];
                ull a0 = pack2(a2.x, a2.x);
                ull a1 = pack2(a2.y, a2.y);
                fma2(acc[0][0], a0, b0);
                fma2(acc[0][1], a0, b1);
                fma2(acc[1][0], a1, b0);
                fma2(acc[1][1], a1, b1);
            }
            __syncthreads();
        }
    }

    float2 bh2[2];
#pragma unroll
    for (int j = 0; j < 2; j++)
        bh2[j] = *reinterpret_cast<const float2*>(&bh[bn + tx * 4 + j * 2]);

#pragma unroll
    for (int i = 0; i < 2; i++) {
        const int m = bm + ty * 2 + i;
        float* row = hid + (size_t)m * SR + (size_t)t * H_ + bn + tx * 4;
#pragma unroll
        for (int j = 0; j < 2; j++) {
            F2U u; u.u = acc[i][j];
            float2 c0 = *reinterpret_cast<const float2*>(row + j * 2);
            float vx = u.f.x + c0.x + bh2[j].x;
            float vy = u.f.y + c0.y + bh2[j].y;
            vx = vx > 0.0f ? vx : 0.0f;
            vy = vy > 0.0f ? vy : 0.0f;
            *reinterpret_cast<float2*>(row + j * 2) = make_float2(vx, vy);
        }
    }
}

// ---------------------------------------------------------------------------
extern "C" void kernel_launch(void* const* d_in, const int* in_sizes, int n_in,
                              void* d_out, int out_size)
{
    (void)in_sizes; (void)n_in; (void)out_size;
    const float* x    = (const float*)d_in[0];
    const float* W_in = (const float*)d_in[1];
    const float* b_in = (const float*)d_in[2];
    const float* W_h  = (const float*)d_in[3];
    const float* b_h  = (const float*)d_in[4];
    const float* W_o  = (const float*)d_in[5];
    const float* b_o  = (const float*)d_in[6];

    float* out = (float*)d_out;                       // (B, T, O)
    float* hid = out + (size_t)B_ * T_ * O_;          // (B, T, H) — also xw scratch

    dim3 blk(256);

    // Phase 1: xw = x @ W_in^T + b_in  -> hid (pre-activation input drive)
    gemm_nt_128<<<dim3((B_ * T_) / 128, H_ / 128), blk>>>(
        x, I_, W_in, I_, b_in, hid, H_, I_);

    // Phase 2: 512 dependent recurrence steps (in-place over hid)
    for (int t = 0; t < T_; ++t)
        rnn_step<<<dim3(B_ / 32, H_ / 64), blk>>>(W_h, b_h, hid, t);

    // Phase 3: output = hidden @ W_o^T + b_o
    gemm_nt_128<<<dim3((B_ * T_) / 128, O_ / 128), blk>>>(
        hid, H_, W_o, H_, b_o, out, O_, H_);
}

// round 2
// speedup vs baseline: 1.1503x; 1.1503x over previous
#include <cuda_runtime.h>
#include <cstdint>
#include <cstddef>

#define B_ 256
#define T_ 512
#define I_ 512
#define H_ 1024
#define O_ 128

#define NCTA 128
#define BS_STRIDE 36                      // padded W_h row stride (floats), 16B-aligned
#define SMEM_FLOATS (1024*BS_STRIDE + 2*32*128)
#define SMEM_BYTES  (SMEM_FLOATS*4)

typedef unsigned long long ull;
union F2U { float2 f; ull u; };
union F4U { float4 f4; ull u[2]; };

__device__ __forceinline__ ull pack2(float lo, float hi) {
    ull r; asm("mov.b64 %0, {%1, %2};" : "=l"(r) : "f"(lo), "f"(hi)); return r;
}
__device__ __forceinline__ void fma2(ull &acc, ull a, ull b) {
    asm("fma.rn.f32x2 %0, %1, %2, %0;" : "+l"(acc) : "l"(a), "l"(b));
}

// Grid-barrier state. g_arrive is monotonic (never reset); g_base is advanced
// once per launch by CTA0 after the final barrier. Spin uses >=, so a late
// spinner from this launch can never deadlock on a future launch's increments.
__device__ ull g_arrive = 0;
__device__ ull g_base   = 0;

// ---------------------------------------------------------------------------
// Persistent recurrence kernel. 128 CTAs, 256 threads.
// CTA (bmi, bni): batch rows [bmi*64, +64), hidden cols [bni*32, +32).
// W_h slice (32 cols x 1024 k) lives in SMEM for the entire kernel.
// Per step: stream h_{t-1} tile (64x1024) in BK=32 chunks, double-buffered,
// duplicate-packed so the inner loop is LDS.128(a)+LDS.128(b)+4x fma.f32x2.
// ---------------------------------------------------------------------------
__global__ __launch_bounds__(256, 1)
void rnn_persist(const float* __restrict__ Wh, const float* __restrict__ bh,
                 float* __restrict__ hid)
{
    extern __shared__ float sm[];
    float* Bs = sm;                       // [1024][BS_STRIDE]
    float* As = sm + 1024 * BS_STRIDE;    // [2][32][128] duplicate-packed

    const int tid = threadIdx.x;
    const int cid = blockIdx.x;
    const int bm  = (cid >> 5) * 64;      // 4 bm tiles
    const int bn  = (cid & 31) * 32;      // 32 bn tiles
    const int tx  = tid & 7;              // 8 x 4 cols = 32 n
    const int ty  = tid >> 3;             // 32 x 2 rows = 64 m
    const size_t SR = (size_t)T_ * H_;

    const ull base = *(volatile ull*)&g_base;

    // ---- One-time W_h slice preload: Bs[k][nl] = Wh[bn+nl][k] ----
    {
        const int nl = tid >> 3;          // 0..31
        const int kq = (tid & 7) * 4;
        const float* wr = Wh + (size_t)(bn + nl) * H_ + kq;
#pragma unroll 4
        for (int j = 0; j < 32; j++) {
            float4 v = *reinterpret_cast<const float4*>(wr + j * 32);
            int k = kq + j * 32;
            Bs[(k + 0) * BS_STRIDE + nl] = v.x;
            Bs[(k + 1) * BS_STRIDE + nl] = v.y;
            Bs[(k + 2) * BS_STRIDE + nl] = v.z;
            Bs[(k + 3) * BS_STRIDE + nl] = v.w;
        }
    }

    const float4 bh4 = *reinterpret_cast<const float4*>(bh + bn + tx * 4);

    // Staging role: thread owns row sr, k-slot kh8..kh8+7 of each 32-k chunk.
    const int sr  = tid & 63;
    const int kh8 = (tid >> 6) * 8;
    const float* arow_base = hid + (size_t)(bm + sr) * SR + kh8;  // +(t-1)*H + c*32
    float* hm0 = hid + (size_t)(bm + ty * 2) * SR + bn + tx * 4;  // + t*H

    __syncthreads();

    for (int t = 0; t < T_; t++) {
        ull a00 = 0, a01 = 0, a10 = 0, a11 = 0;

        if (t > 0) {
            const float* ar = arow_base + (size_t)(t - 1) * H_;

            // prologue: chunk 0 -> As[0]
            {
                F4U r0, r1;
                r0.f4 = *reinterpret_cast<const float4*>(ar);
                r1.f4 = *reinterpret_cast<const float4*>(ar + 4);
                float* d = As;
                *reinterpret_cast<ull*>(d + (kh8 + 0) * 128 + 2 * sr) = pack2(r0.f4.x, r0.f4.x);
                *reinterpret_cast<ull*>(d + (kh8 + 1) * 128 + 2 * sr) = pack2(r0.f4.y, r0.f4.y);
                *reinterpret_cast<ull*>(d + (kh8 + 2) * 128 + 2 * sr) = pack2(r0.f4.z, r0.f4.z);
                *reinterpret_cast<ull*>(d + (kh8 + 3) * 128 + 2 * sr) = pack2(r0.f4.w, r0.f4.w);
                *reinterpret_cast<ull*>(d + (kh8 + 4) * 128 + 2 * sr) = pack2(r1.f4.x, r1.f4.x);
                *reinterpret_cast<ull*>(d + (kh8 + 5) * 128 + 2 * sr) = pack2(r1.f4.y, r1.f4.y);
                *reinterpret_cast<ull*>(d + (kh8 + 6) * 128 + 2 * sr) = pack2(r1.f4.z, r1.f4.z);
                *reinterpret_cast<ull*>(d + (kh8 + 7) * 128 + 2 * sr) = pack2(r1.f4.w, r1.f4.w);
            }

            for (int c = 0; c < 32; c++) {
                __syncthreads();                 // As[c&1] ready; prior reads done
                F4U n0, n1;
                if (c < 31) {
                    const float* na = ar + (c + 1) * 32;
                    n0.f4 = *reinterpret_cast<const float4*>(na);
                    n1.f4 = *reinterpret_cast<const float4*>(na + 4);
                }
                const float* ap = As + (c & 1) * 4096 + ty * 4;
                const float* bp = Bs + c * 32 * BS_STRIDE + tx * 4;
#pragma unroll
                for (int kk = 0; kk < 32; kk++) {
                    F4U av, bv;
                    av.f4 = *reinterpret_cast<const float4*>(ap + kk * 128);
                    bv.f4 = *reinterpret_cast<const float4*>(bp + kk * BS_STRIDE);
                    fma2(a00, av.u[0], bv.u[0]);
                    fma2(a01, av.u[0], bv.u[1]);
                    fma2(a10, av.u[1], bv.u[0]);
                    fma2(a11, av.u[1], bv.u[1]);
                }
                if (c < 31) {
                    float* d = As + ((c + 1) & 1) * 4096;
                    *reinterpret_cast<ull*>(d + (kh8 + 0) * 128 + 2 * sr) = pack2(n0.f4.x, n0.f4.x);
                    *reinterpret_cast<ull*>(d + (kh8 + 1) * 128 + 2 * sr) = pack2(n0.f4.y, n0.f4.y);
                    *reinterpret_cast<ull*>(d + (kh8 + 2) * 128 + 2 * sr) = pack2(n0.f4.z, n0.f4.z);
                    *reinterpret_cast<ull*>(d + (kh8 + 3) * 128 + 2 * sr) = pack2(n0.f4.w, n0.f4.w);
                    *reinterpret_cast<ull*>(d + (kh8 + 4) * 128 + 2 * sr) = pack2(n1.f4.x, n1.f4.x);
                    *reinterpret_cast<ull*>(d + (kh8 + 5) * 128 + 2 * sr) = pack2(n1.f4.y, n1.f4.y);
                    *reinterpret_cast<ull*>(d + (kh8 + 6) * 128 + 2 * sr) = pack2(n1.f4.z, n1.f4.z);
                    *reinterpret_cast<ull*>(d + (kh8 + 7) * 128 + 2 * sr) = pack2(n1.f4.w, n1.f4.w);
                }
            }
        }

        // ---- Epilogue: h_t = relu(xw_t + acc + b_h), in place ----
        {
            float* o0 = hm0 + (size_t)t * H_;
            float* o1 = o0 + SR;
            float4 x0 = *reinterpret_cast<const float4*>(o0);
            float4 x1 = *reinterpret_cast<const float4*>(o1);
            F2U u; float4 y0, y1;
            u.u = a00; y0.x = fmaxf(x0.x + u.f.x + bh4.x, 0.f);
                       y0.y = fmaxf(x0.y + u.f.y + bh4.y, 0.f);
            u.u = a01; y0.z = fmaxf(x0.z + u.f.x + bh4.z, 0.f);
                       y0.w = fmaxf(x0.w + u.f.y + bh4.w, 0.f);
            u.u = a10; y1.x = fmaxf(x1.x + u.f.x + bh4.x, 0.f);
                       y1.y = fmaxf(x1.y + u.f.y + bh4.y, 0.f);
            u.u = a11; y1.z = fmaxf(x1.z + u.f.x + bh4.z, 0.f);
                       y1.w = fmaxf(x1.w + u.f.y + bh4.w, 0.f);
            *reinterpret_cast<float4*>(o0) = y0;
            *reinterpret_cast<float4*>(o1) = y1;
        }

        // ---- Grid barrier ----
        __syncthreads();
        if (tid == 0) {
            __threadfence();
            atomicAdd(&g_arrive, 1ULL);
            const ull tgt = base + (ull)(t + 1) * NCTA;
            while (*(volatile ull*)&g_arrive < tgt) { }
            __threadfence();
        }
        __syncthreads();
    }

    if (cid == 0 && tid == 0) g_base = base + (ull)T_ * NCTA;
}

// ---------------------------------------------------------------------------
// C = A @ B^T + bias  (unchanged from round 1 — verified correct)
// ---------------------------------------------------------------------------
__global__ __launch_bounds__(256, 2)
void gemm_nt_128(const float* __restrict__ A, int lda,
                 const float* __restrict__ Bm, int ldb,
                 const float* __restrict__ bias,
                 float* __restrict__ C, int ldc, int K)
{
    __shared__ float As[8][128];
    __shared__ float Bs[8][128];
    const int bm = blockIdx.x * 128;
    const int bn = blockIdx.y * 128;
    const int tid = threadIdx.x;
    const int tx = tid & 15;
    const int ty = tid >> 4;
    const int lrow = tid >> 1;
    const int lcol = (tid & 1) * 4;

    const float* Ap = A + (size_t)(bm + lrow) * lda + lcol;
    const float* Bp = Bm + (size_t)(bn + lrow) * ldb + lcol;

    ull acc[8][4];
#pragma unroll
    for (int i = 0; i < 8; i++)
#pragma unroll
        for (int j = 0; j < 4; j++) acc[i][j] = 0ULL;

    for (int k0 = 0; k0 < K; k0 += 8) {
        float4 av = *reinterpret_cast<const float4*>(Ap + k0);
        float4 bv = *reinterpret_cast<const float4*>(Bp + k0);
        As[lcol + 0][lrow] = av.x; As[lcol + 1][lrow] = av.y;
        As[lcol + 2][lrow] = av.z; As[lcol + 3][lrow] = av.w;
        Bs[lcol + 0][lrow] = bv.x; Bs[lcol + 1][lrow] = bv.y;
        Bs[lcol + 2][lrow] = bv.z; Bs[lcol + 3][lrow] = bv.w;
        __syncthreads();
#pragma unroll
        for (int kk = 0; kk < 8; kk++) {
            float4 a0 = *reinterpret_cast<const float4*>(&As[kk][ty * 8]);
            float4 a1 = *reinterpret_cast<const float4*>(&As[kk][ty * 8 + 4]);
            const ull* bp = reinterpret_cast<const ull*>(&Bs[kk][tx * 8]);
            ull b0 = bp[0], b1 = bp[1], b2 = bp[2], b3 = bp[3];
            float am[8] = {a0.x, a0.y, a0.z, a0.w, a1.x, a1.y, a1.z, a1.w};
#pragma unroll
            for (int i = 0; i < 8; i++) {
                ull ad = pack2(am[i], am[i]);
                fma2(acc[i][0], ad, b0);
                fma2(acc[i][1], ad, b1);
                fma2(acc[i][2], ad, b2);
                fma2(acc[i][3], ad, b3);
            }
        }
        __syncthreads();
    }

    float2 bias2[4];
#pragma unroll
    for (int j = 0; j < 4; j++)
        bias2[j] = *reinterpret_cast<const float2*>(&bias[bn + tx * 8 + j * 2]);

#pragma unroll
    for (int i = 0; i < 8; i++) {
        float* Crow = C + (size_t)(bm + ty * 8 + i) * ldc + bn + tx * 8;
#pragma unroll
        for (int j = 0; j < 4; j++) {
            F2U u; u.u = acc[i][j];
            u.f.x += bias2[j].x;
            u.f.y += bias2[j].y;
            *reinterpret_cast<float2*>(Crow + j * 2) = u.f;
        }
    }
}

// ---------------------------------------------------------------------------
extern "C" void kernel_launch(void* const* d_in, const int* in_sizes, int n_in,
                              void* d_out, int out_size)
{
    (void)in_sizes; (void)n_in; (void)out_size;
    const float* x    = (const float*)d_in[0];
    const float* W_in = (const float*)d_in[1];
    const float* b_in = (const float*)d_in[2];
    const float* W_h  = (const float*)d_in[3];
    const float* b_h  = (const float*)d_in[4];
    const float* W_o  = (const float*)d_in[5];
    const float* b_o  = (const float*)d_in[6];

    float* out = (float*)d_out;                       // (B, T, O)
    float* hid = out + (size_t)B_ * T_ * O_;          // (B, T, H) — also xw scratch

    cudaFuncSetAttribute(rnn_persist,
                         cudaFuncAttributeMaxDynamicSharedMemorySize, SMEM_BYTES);

    dim3 blk(256);

    // Phase 1: xw = x @ W_in^T + b_in  -> hid
    gemm_nt_128<<<dim3((B_ * T_) / 128, H_ / 128), blk>>>(
        x, I_, W_in, I_, b_in, hid, H_, I_);

    // Phase 2: all 512 recurrence steps in one persistent kernel
    rnn_persist<<<NCTA, blk, SMEM_BYTES>>>(W_h, b_h, hid);

    // Phase 3: output = hidden @ W_o^T + b_o
    gemm_nt_128<<<dim3((B_ * T_) / 128, O_ / 128), blk>>>(
        hid, H_, W_o, H_, b_o, out, O_, H_);
}

// round 3
// speedup vs baseline: 1.2600x; 1.0953x over previous
#include <cuda_runtime.h>
#include <cstdint>
#include <cstddef>

#define B_ 256
#define T_ 512
#define I_ 512
#define H_ 1024
#define O_ 128

#define NCTA 128
#define THREADS 512

// smem: As [4 kg][2 buf][32 k][128 dup-m floats] = 32768 floats
//       Bs [4 kg][2 buf][32 k][36 pad]          =  9216 floats
#define AS_FLOATS 32768
#define SMEM_FLOATS (AS_FLOATS + 9216)
#define SMEM_BYTES  (SMEM_FLOATS * 4)

typedef unsigned long long ull;
union F2U { float2 f; ull u; };
union F4U { float4 f4; ull u[2]; };

__device__ __forceinline__ ull pack2(float lo, float hi) {
    ull r; asm("mov.b64 %0, {%1, %2};" : "=l"(r) : "f"(lo), "f"(hi)); return r;
}
__device__ __forceinline__ void fma2(ull &acc, ull a, ull b) {
    asm("fma.rn.f32x2 %0, %1, %2, %0;" : "+l"(acc) : "l"(a), "l"(b));
}
__device__ __forceinline__ void add2(ull &acc, ull v) {
    asm("add.rn.f32x2 %0, %0, %1;" : "+l"(acc) : "l"(v));
}

// Monotonic grid-barrier state (never reset; base advanced once per launch).
__device__ ull g_arrive = 0;
__device__ ull g_base   = 0;

// ---------------------------------------------------------------------------
// Persistent recurrence. 128 CTAs x 512 threads (16 warps/SM, 1 CTA/SM).
// CTA tile: 64 (batch m) x 32 (hidden n). K=1024 split over 4 thread groups
// (kg) of 128 threads; each thread computes a 4m x 4n tile over K/4, partials
// reduced through smem at step end. Inner loop: 3x LDS.128 + 8x fma.f32x2.
// A (h_{t-1}) and W_h slices streamed from L2 per step, double-buffered,
// A duplicate-packed for f32x2.
// ---------------------------------------------------------------------------
__global__ __launch_bounds__(THREADS, 1)
void rnn_persist(const float* __restrict__ Wh, const float* __restrict__ bh,
                 float* __restrict__ hid)
{
    extern __shared__ float sm[];
    float* As = sm;                  // [kg][buf][32][128]
    float* Bs = sm + AS_FLOATS;      // [kg][buf][32][36]
    ull*   Red = reinterpret_cast<ull*>(sm);  // [8][3][128] (reuses As)

    const int tid = threadIdx.x;
    const int cid = blockIdx.x;
    const int bm  = (cid >> 5) * 64;
    const int bn  = (cid & 31) * 32;
    const int kg  = tid >> 7;        // k-group 0..3
    const int l   = tid & 127;
    const int tx  = l & 7;           // 8 x 4 n
    const int ty  = l >> 3;          // 16 x 4 m
    const size_t SR = (size_t)T_ * H_;

    // Staging roles
    const int arow = l & 63;
    const int akq  = (l >> 6) * 16;  // k-offset 0 or 16 within chunk
    const int bnl  = l & 31;
    const int bkq  = (l >> 5) * 8;   // k-offset 0,8,16,24 within chunk

    const float* Abase = hid + (size_t)(bm + arow) * SR + kg * 256 + akq;   // +(t-1)*H + c*32
    const float* Wbase = Wh  + (size_t)(bn + bnl) * H_ + kg * 256 + bkq;    // + c*32
    float* AsP = As + kg * 8192 + akq * 128 + 2 * arow;                     // + buf*4096 + (u*4+e)*128
    float* BsP = Bs + kg * 2304 + bkq * 36 + bnl;                           // + buf*1152 + (u*4+e)*36
    const float* avP = As + kg * 8192 + ty * 8;                             // + buf*4096 + kk*128
    const float* bvP = Bs + kg * 2304 + tx * 4;                             // + buf*1152 + kk*36

    const float4 bh4 = *reinterpret_cast<const float4*>(bh + bn + tx * 4);
    const ull base = *(volatile ull*)&g_base;

    for (int t = 0; t < T_; t++) {
        ull acc[4][2];
#pragma unroll
        for (int i = 0; i < 4; i++) { acc[i][0] = 0ULL; acc[i][1] = 0ULL; }

        if (t > 0) {
            const float* Ak = Abase + (size_t)(t - 1) * H_;
            float4 ra0, ra1, ra2, ra3, rb0, rb1;

            // prologue: load + stage chunk 0 into buf 0
            ra0 = *reinterpret_cast<const float4*>(Ak + 0);
            ra1 = *reinterpret_cast<const float4*>(Ak + 4);
            ra2 = *reinterpret_cast<const float4*>(Ak + 8);
            ra3 = *reinterpret_cast<const float4*>(Ak + 12);
            rb0 = *reinterpret_cast<const float4*>(Wbase + 0);
            rb1 = *reinterpret_cast<const float4*>(Wbase + 4);
            {
                float* d = AsP;
                d[0*128] = ra0.x; d[0*128+1] = ra0.x;  // written as pairs below instead
            }
            // dup-packed A stores (ull writes), chunk 0
            {
                float* d = AsP;
                *reinterpret_cast<ull*>(d +  0*128) = pack2(ra0.x, ra0.x);
                *reinterpret_cast<ull*>(d +  1*128) = pack2(ra0.y, ra0.y);
                *reinterpret_cast<ull*>(d +  2*128) = pack2(ra0.z, ra0.z);
                *reinterpret_cast<ull*>(d +  3*128) = pack2(ra0.w, ra0.w);
                *reinterpret_cast<ull*>(d +  4*128) = pack2(ra1.x, ra1.x);
                *reinterpret_cast<ull*>(d +  5*128) = pack2(ra1.y, ra1.y);
                *reinterpret_cast<ull*>(d +  6*128) = pack2(ra1.z, ra1.z);
                *reinterpret_cast<ull*>(d +  7*128) = pack2(ra1.w, ra1.w);
                *reinterpret_cast<ull*>(d +  8*128) = pack2(ra2.x, ra2.x);
                *reinterpret_cast<ull*>(d +  9*128) = pack2(ra2.y, ra2.y);
                *reinterpret_cast<ull*>(d + 10*128) = pack2(ra2.z, ra2.z);
                *reinterpret_cast<ull*>(d + 11*128) = pack2(ra2.w, ra2.w);
                *reinterpret_cast<ull*>(d + 12*128) = pack2(ra3.x, ra3.x);
                *reinterpret_cast<ull*>(d + 13*128) = pack2(ra3.y, ra3.y);
                *reinterpret_cast<ull*>(d + 14*128) = pack2(ra3.z, ra3.z);
                *reinterpret_cast<ull*>(d + 15*128) = pack2(ra3.w, ra3.w);
                float* b = BsP;
                b[0*36] = rb0.x; b[1*36] = rb0.y; b[2*36] = rb0.z; b[3*36] = rb0.w;
                b[4*36] = rb1.x; b[5*36] = rb1.y; b[6*36] = rb1.z; b[7*36] = rb1.w;
            }
            __syncthreads();

            for (int c = 0; c < 8; c++) {
                const int buf = c & 1;
                if (c < 7) {
                    const float* An = Ak + (c + 1) * 32;
                    ra0 = *reinterpret_cast<const float4*>(An + 0);
                    ra1 = *reinterpret_cast<const float4*>(An + 4);
                    ra2 = *reinterpret_cast<const float4*>(An + 8);
                    ra3 = *reinterpret_cast<const float4*>(An + 12);
                    const float* Wn = Wbase + (c + 1) * 32;
                    rb0 = *reinterpret_cast<const float4*>(Wn + 0);
                    rb1 = *reinterpret_cast<const float4*>(Wn + 4);
                }
                const float* ap = avP + buf * 4096;
                const float* bp = bvP + buf * 1152;
#pragma unroll
                for (int kk = 0; kk < 32; kk++) {
                    F4U a01, a23, bv;
                    a01.f4 = *reinterpret_cast<const float4*>(ap + kk * 128);
                    a23.f4 = *reinterpret_cast<const float4*>(ap + kk * 128 + 4);
                    bv.f4  = *reinterpret_cast<const float4*>(bp + kk * 36);
                    fma2(acc[0][0], a01.u[0], bv.u[0]);
                    fma2(acc[0][1], a01.u[0], bv.u[1]);
                    fma2(acc[1][0], a01.u[1], bv.u[0]);
                    fma2(acc[1][1], a01.u[1], bv.u[1]);
                    fma2(acc[2][0], a23.u[0], bv.u[0]);
                    fma2(acc[2][1], a23.u[0], bv.u[1]);
                    fma2(acc[3][0], a23.u[1], bv.u[0]);
                    fma2(acc[3][1], a23.u[1], bv.u[1]);
                }
                if (c < 7) {
                    const int nb = buf ^ 1;
                    float* d = AsP + nb * 4096;
                    *reinterpret_cast<ull*>(d +  0*128) = pack2(ra0.x, ra0.x);
                    *reinterpret_cast<ull*>(d +  1*128) = pack2(ra0.y, ra0.y);
                    *reinterpret_cast<ull*>(d +  2*128) = pack2(ra0.z, ra0.z);
                    *reinterpret_cast<ull*>(d +  3*128) = pack2(ra0.w, ra0.w);
                    *reinterpret_cast<ull*>(d +  4*128) = pack2(ra1.x, ra1.x);
                    *reinterpret_cast<ull*>(d +  5*128) = pack2(ra1.y, ra1.y);
                    *reinterpret_cast<ull*>(d +  6*128) = pack2(ra1.z, ra1.z);
                    *reinterpret_cast<ull*>(d +  7*128) = pack2(ra1.w, ra1.w);
                    *reinterpret_cast<ull*>(d +  8*128) = pack2(ra2.x, ra2.x);
                    *reinterpret_cast<ull*>(d +  9*128) = pack2(ra2.y, ra2.y);
                    *reinterpret_cast<ull*>(d + 10*128) = pack2(ra2.z, ra2.z);
                    *reinterpret_cast<ull*>(d + 11*128) = pack2(ra2.w, ra2.w);
                    *reinterpret_cast<ull*>(d + 12*128) = pack2(ra3.x, ra3.x);
                    *reinterpret_cast<ull*>(d + 13*128) = pack2(ra3.y, ra3.y);
                    *reinterpret_cast<ull*>(d + 14*128) = pack2(ra3.z, ra3.z);
                    *reinterpret_cast<ull*>(d + 15*128) = pack2(ra3.w, ra3.w);
                    float* b = BsP + nb * 1152;
                    b[0*36] = rb0.x; b[1*36] = rb0.y; b[2*36] = rb0.z; b[3*36] = rb0.w;
                    b[4*36] = rb1.x; b[5*36] = rb1.y; b[6*36] = rb1.z; b[7*36] = rb1.w;
                }
                __syncthreads();
            }

            // Reduce the 4 k-group partials (Red reuses As region; safe after sync)
            if (kg > 0) {
                ull* r = Red + (kg - 1) * 128 + l;
#pragma unroll
                for (int i = 0; i < 4; i++) {
                    r[(i * 2 + 0) * 384] = acc[i][0];
                    r[(i * 2 + 1) * 384] = acc[i][1];
                }
            }
            __syncthreads();
            if (kg == 0) {
#pragma unroll
                for (int i = 0; i < 4; i++) {
#pragma unroll
                    for (int j = 0; j < 2; j++) {
                        const ull* r = Red + (i * 2 + j) * 384 + l;
                        add2(acc[i][j], r[0]);
                        add2(acc[i][j], r[128]);
                        add2(acc[i][j], r[256]);
                    }
                }
            }
        }

        // Epilogue: h_t = relu(xw_t + acc + b_h), in place (kg0 threads only)
        if (kg == 0) {
#pragma unroll
            for (int i = 0; i < 4; i++) {
                float* o = hid + (size_t)(bm + ty * 4 + i) * SR + (size_t)t * H_ + bn + tx * 4;
                float4 x = *reinterpret_cast<const float4*>(o);
                F2U u0, u1; u0.u = acc[i][0]; u1.u = acc[i][1];
                float4 y;
                y.x = fmaxf(x.x + u0.f.x + bh4.x, 0.f);
                y.y = fmaxf(x.y + u0.f.y + bh4.y, 0.f);
                y.z = fmaxf(x.z + u1.f.x + bh4.z, 0.f);
                y.w = fmaxf(x.w + u1.f.y + bh4.w, 0.f);
                *reinterpret_cast<float4*>(o) = y;
            }
            __threadfence();   // release h_t before the barrier signal
        }

        // Grid barrier
        __syncthreads();
        if (tid == 0) {
            atomicAdd(&g_arrive, 1ULL);
            const ull tgt = base + (ull)(t + 1) * NCTA;
            while (*(volatile ull*)&g_arrive < tgt) { }
            __threadfence();
        }
        __syncthreads();
    }

    if (cid == 0 && tid == 0) g_base = base + (ull)T_ * NCTA;
}

// ---------------------------------------------------------------------------
// C = A @ B^T + bias (unchanged; handles phases 1 and 3)
// ---------------------------------------------------------------------------
__global__ __launch_bounds__(256, 2)
void gemm_nt_128(const float* __restrict__ A, int lda,
                 const float* __restrict__ Bm, int ldb,
                 const float* __restrict__ bias,
                 float* __restrict__ C, int ldc, int K)
{
    __shared__ float As[8][128];
    __shared__ float Bs[8][128];
    const int bm = blockIdx.x * 128;
    const int bn = blockIdx.y * 128;
    const int tid = threadIdx.x;
    const int tx = tid & 15;
    const int ty = tid >> 4;
    const int lrow = tid >> 1;
    const int lcol = (tid & 1) * 4;

    const float* Ap = A + (size_t)(bm + lrow) * lda + lcol;
    const float* Bp = Bm + (size_t)(bn + lrow) * ldb + lcol;

    ull acc[8][4];
#pragma unroll
    for (int i = 0; i < 8; i++)
#pragma unroll
        for (int j = 0; j < 4; j++) acc[i][j] = 0ULL;

    for (int k0 = 0; k0 < K; k0 += 8) {
        float4 av = *reinterpret_cast<const float4*>(Ap + k0);
        float4 bv = *reinterpret_cast<const float4*>(Bp + k0);
        As[lcol + 0][lrow] = av.x; As[lcol + 1][lrow] = av.y;
        As[lcol + 2][lrow] = av.z; As[lcol + 3][lrow] = av.w;
        Bs[lcol + 0][lrow] = bv.x; Bs[lcol + 1][lrow] = bv.y;
        Bs[lcol + 2][lrow] = bv.z; Bs[lcol + 3][lrow] = bv.w;
        __syncthreads();
#pragma unroll
        for (int kk = 0; kk < 8; kk++) {
            float4 a0 = *reinterpret_cast<const float4*>(&As[kk][ty * 8]);
            float4 a1 = *reinterpret_cast<const float4*>(&As[kk][ty * 8 + 4]);
            const ull* bp = reinterpret_cast<const ull*>(&Bs[kk][tx * 8]);
            ull b0 = bp[0], b1 = bp[1], b2 = bp[2], b3 = bp[3];
            float am[8] = {a0.x, a0.y, a0.z, a0.w, a1.x, a1.y, a1.z, a1.w};
#pragma unroll
            for (int i = 0; i < 8; i++) {
                ull ad = pack2(am[i], am[i]);
                fma2(acc[i][0], ad, b0);
                fma2(acc[i][1], ad, b1);
                fma2(acc[i][2], ad, b2);
                fma2(acc[i][3], ad, b3);
            }
        }
        __syncthreads();
    }

    float2 bias2[4];
#pragma unroll
    for (int j = 0; j < 4; j++)
        bias2[j] = *reinterpret_cast<const float2*>(&bias[bn + tx * 8 + j * 2]);

#pragma unroll
    for (int i = 0; i < 8; i++) {
        float* Crow = C + (size_t)(bm + ty * 8 + i) * ldc + bn + tx * 8;
#pragma unroll
        for (int j = 0; j < 4; j++) {
            F2U u; u.u = acc[i][j];
            u.f.x += bias2[j].x;
            u.f.y += bias2[j].y;
            *reinterpret_cast<float2*>(Crow + j * 2) = u.f;
        }
    }
}

// ---------------------------------------------------------------------------
extern "C" void kernel_launch(void* const* d_in, const int* in_sizes, int n_in,
                              void* d_out, int out_size)
{
    (void)in_sizes; (void)n_in; (void)out_size;
    const float* x    = (const float*)d_in[0];
    const float* W_in = (const float*)d_in[1];
    const float* b_in = (const float*)d_in[2];
    const float* W_h  = (const float*)d_in[3];
    const float* b_h  = (const float*)d_in[4];
    const float* W_o  = (const float*)d_in[5];
    const float* b_o  = (const float*)d_in[6];

    float* out = (float*)d_out;                       // (B, T, O)
    float* hid = out + (size_t)B_ * T_ * O_;          // (B, T, H) — also xw scratch

    cudaFuncSetAttribute(rnn_persist,
                         cudaFuncAttributeMaxDynamicSharedMemorySize, SMEM_BYTES);

    // Phase 1: xw = x @ W_in^T + b_in  -> hid
    gemm_nt_128<<<dim3((B_ * T_) / 128, H_ / 128), dim3(256)>>>(
        x, I_, W_in, I_, b_in, hid, H_, I_);

    // Phase 2: all 512 recurrence steps in one persistent kernel
    rnn_persist<<<NCTA, dim3(THREADS), SMEM_BYTES>>>(W_h, b_h, hid);

    // Phase 3: output = hidden @ W_o^T + b_o
    gemm_nt_128<<<dim3((B_ * T_) / 128, O_ / 128), dim3(256)>>>(
        hid, H_, W_o, H_, b_o, out, O_, H_);
}